// round 13
// baseline (speedup 1.0000x reference)
#include <cuda_runtime.h>
#include <cuda_fp16.h>
#include <cstdint>

// ---------------- problem constants ----------------
#define CIN   256
#define KOUT  256
#define HH    56
#define WW    56
#define NPF   2304           // 256*3*3 per output filter
#define PH    58
#define PW    58
#define NIMG  32
#define PIX   (HH*WW)        // 3136
#define MTOT  (NIMG*PIX)     // 100352

// ---------------- GEMM tiling ----------------
#define MT    192            // CTA M tile (ragged tail: last tile covers 128)
#define NT    64             // CTA N tile
#define KC    32             // K chunk (halfs)
#define NCH   72             // 9 taps * 8 chunks of 32 channels
#define NS    4              // pipeline stages
#define NTHR  192            // 6 warps (3m x 2n); 2 CTAs/SM -> 170 regs/thread

// smem stage: A only (192 rows x 80B); 80B stride -> conflict-free ldsm
#define ROWB  80
#define ASTG  (MT*ROWB)      // 15360
#define STG   ASTG
#define SMDYN (NS*STG)       // 61440

// ---------------- device scratch ----------------
__device__ __half   g_b[9 * KOUT * CIN];                 // [rs][k][c], +-1 (pack source)
__device__ float    g_alpha[KOUT];
__device__ __half   g_xpad[(size_t)NIMG * PH * PW * CIN];// [n][hp][wp][c]
// packed ternary B fragments: [chunk72][nblk8][kk2][lane32] -> uint32 (16 x 2-bit)
__device__ uint32_t g_bq[NCH * 8 * 2 * 32];

// ---------------- ptx helpers (family-portable only) ----------------
__device__ __forceinline__ void cp16(uint32_t dst, const void* src) {
    asm volatile("cp.async.cg.shared.global [%0], [%1], 16;"
                 :: "r"(dst), "l"(__cvta_generic_to_global(src)) : "memory");
}
#define CP_COMMIT()  asm volatile("cp.async.commit_group;" ::: "memory")
#define CP_WAIT(N)   asm volatile("cp.async.wait_group %0;" :: "n"(N) : "memory")

#define LDSM4(R, addr)                                                        \
    asm volatile("ldmatrix.sync.aligned.m8n8.x4.shared.b16 {%0,%1,%2,%3}, [%4];" \
                 : "=r"((R)[0]), "=r"((R)[1]), "=r"((R)[2]), "=r"((R)[3])     \
                 : "r"(addr))

#define MMA16816(D, A, B0, B1)                                                \
    asm volatile("mma.sync.aligned.m16n8k16.row.col.f32.f16.f16.f32 "         \
                 "{%0,%1,%2,%3}, {%4,%5,%6,%7}, {%8,%9}, {%0,%1,%2,%3};"      \
                 : "+f"((D)[0]), "+f"((D)[1]), "+f"((D)[2]), "+f"((D)[3])     \
                 : "r"((A)[0]), "r"((A)[1]), "r"((A)[2]), "r"((A)[3]),        \
                   "r"(B0), "r"(B1))

// decode 2 ternary fields (bits[0:2),[2:4) of q) -> fp16x2 {tab[v0], tab[v1]}
// tab: 0->0x0000, 1->0x3C00(+1), 2->0xBC00(-1). Low byte of each half is 0.
__device__ __forceinline__ uint32_t dec2(uint32_t q) {
    uint32_t sel = ((q & 3u) << 4) | ((q & 0xCu) << 10);
    uint32_t r;
    asm("prmt.b32 %0, %1, %2, %3;" : "=r"(r)
        : "r"(0x00BC3C00u), "r"(0u), "r"(sel));
    return r;
}

// ---------------------------------------------------------------------------
// K0: ternarize (float4 + warp shuffle reductions). One block per filter.
// ---------------------------------------------------------------------------
__global__ void ternarize_kernel(const float* __restrict__ w) {
    const int o = blockIdx.x;
    const int tid = threadIdx.x;
    const int lane = tid & 31;
    const int wrp = tid >> 5;
    const float4* wo4 = (const float4*)(w + (size_t)o * NPF);
    __shared__ float red[8];
    __shared__ float s_delta;

    float s = 0.f;
    for (int i = tid; i < NPF / 4; i += 256) {
        float4 v = wo4[i];
        s += fabsf(v.x) + fabsf(v.y) + fabsf(v.z) + fabsf(v.w);
    }
    #pragma unroll
    for (int d = 16; d > 0; d >>= 1) s += __shfl_xor_sync(~0u, s, d);
    if (lane == 0) red[wrp] = s;
    __syncthreads();
    if (tid == 0) {
        float t = 0.f;
        #pragma unroll
        for (int i = 0; i < 8; i++) t += red[i];
        s_delta = (0.7f / (float)NPF) * t;
    }
    __syncthreads();
    const float delta = s_delta;

    float cnt = 0.f, asum = 0.f;
    for (int i = tid; i < NPF / 4; i += 256) {
        float4 v = wo4[i];
        float a;
        a = fabsf(v.x); if (a > delta) { cnt += 1.f; asum += a; }
        a = fabsf(v.y); if (a > delta) { cnt += 1.f; asum += a; }
        a = fabsf(v.z); if (a > delta) { cnt += 1.f; asum += a; }
        a = fabsf(v.w); if (a > delta) { cnt += 1.f; asum += a; }
    }
    #pragma unroll
    for (int d = 16; d > 0; d >>= 1) {
        cnt  += __shfl_xor_sync(~0u, cnt, d);
        asum += __shfl_xor_sync(~0u, asum, d);
    }
    if (lane == 0) red[wrp] = cnt;
    __syncthreads();
    float cnt_tot = 0.f;
    if (tid == 0) {
        #pragma unroll
        for (int i = 0; i < 8; i++) cnt_tot += red[i];
        red[0] = cnt_tot;
    }
    __syncthreads();
    cnt_tot = red[0];
    __syncthreads();
    if (lane == 0) red[wrp] = asum;
    __syncthreads();
    if (tid == 0) {
        float t = 0.f;
        #pragma unroll
        for (int i = 0; i < 8; i++) t += red[i];
        g_alpha[o] = t / cnt_tot;
    }

    const float* wo = w + (size_t)o * NPF;
    for (int i = tid; i < NPF; i += 256) {
        float v = wo[i];
        float t = (v > delta) ? 1.f : ((v < -delta) ? -1.f : 0.f);
        int c = i / 9, rs = i % 9;
        g_b[((size_t)rs * KOUT + o) * CIN + c] = __float2half_rn(t);
    }
}

// ---------------------------------------------------------------------------
// K0b: pack ternary B into fragment-ordered 2-bit words.
// grid (72 chunks, 8 nblk), 64 threads = (kk 0..1, lane 0..31).
// Field f = (j2*2+rr)*2 + h at bits [2f, 2f+2):
//   value = tern[n = nblk*32 + j2*8 + (lane>>2)]
//               [kchan = cc*32 + kk*16 + rr*8 + 2*(lane&3) + h]   (rs = chunk>>3)
// ---------------------------------------------------------------------------
__global__ void pack_b_kernel() {
    const int chunk = blockIdx.x, nblk = blockIdx.y;
    const int kk = threadIdx.x >> 5, l = threadIdx.x & 31;
    const int rs = chunk >> 3, cc = chunk & 7;
    const int c = l & 3;

    uint32_t p = 0;
    #pragma unroll
    for (int j2 = 0; j2 < 4; j2++) {
        int n = nblk * 32 + j2 * 8 + (l >> 2);
        const __half* row = g_b + ((size_t)rs * KOUT + n) * CIN;
        #pragma unroll
        for (int rr = 0; rr < 2; rr++)
            #pragma unroll
            for (int h = 0; h < 2; h++) {
                int kchan = cc * 32 + kk * 16 + rr * 8 + 2 * c + h;
                float v = __half2float(row[kchan]);
                uint32_t code = (v > 0.25f) ? 1u : ((v < -0.25f) ? 2u : 0u);
                int f = (j2 * 2 + rr) * 2 + h;
                p |= code << (2 * f);
            }
    }
    g_bq[((chunk * 8 + nblk) * 2 + kk) * 32 + l] = p;
}

// ---------------------------------------------------------------------------
// K1: pad + NCHW->NHWC transpose + fp16 convert (border rows write zeros).
// ---------------------------------------------------------------------------
__global__ void pad_transpose_kernel(const float* __restrict__ x) {
    __shared__ float s[64][57];
    const int hp = blockIdx.x, c0 = blockIdx.y * 64, n = blockIdx.z;
    __half* dst = g_xpad + ((size_t)(n * PH + hp) * PW) * CIN + c0;

    if (hp == 0 || hp == PH - 1) {
        for (int idx = threadIdx.x; idx < PW * 8; idx += 256) {
            int wp = idx >> 3, u = idx & 7;
            ((uint4*)(dst + (size_t)wp * CIN))[u] = make_uint4(0u, 0u, 0u, 0u);
        }
        return;
    }

    const int h = hp - 1;
    const float* xp = x + ((size_t)(n * CIN + c0) * HH + h) * WW;
    for (int idx = threadIdx.x; idx < 64 * WW; idx += 256) {
        int ci = idx / WW, w = idx - ci * WW;
        s[ci][w] = xp[(size_t)ci * PIX + w];
    }
    __syncthreads();

    for (int idx = threadIdx.x; idx < PW * 64; idx += 256) {
        int wp = idx / 64, ci = idx - wp * 64;
        float v = (wp >= 1 && wp <= WW) ? s[ci][wp - 1] : 0.f;
        dst[(size_t)wp * CIN + ci] = __float2half_rn(v);
    }
}

// ---------------------------------------------------------------------------
// K2: implicit-GEMM conv. A via cp.async+ldmatrix; B decoded from packed
// ternary (2-bit) via LDG+PRMT -> no B smem/LDSM at all.
// Grid (523, 4): CTA = 192 x 64, 6 warps (3m x 2n), warp 64x32, 2 CTAs/SM.
// ---------------------------------------------------------------------------
__global__ void __launch_bounds__(NTHR, 2)
conv_mma_kernel(const float* __restrict__ bias_g, float* __restrict__ out) {
    extern __shared__ __align__(128) char smem[];
    const uint32_t sbase = (uint32_t)__cvta_generic_to_shared(smem);

    const int tid = threadIdx.x;
    const int lane = tid & 31;
    const int wid = tid >> 5;           // 0..5
    const int warp_m = wid >> 1;        // 0..2
    const int warp_n = wid & 1;         // 0..1

    const int p0 = blockIdx.x * MT;
    const int n0 = blockIdx.y * NT;
    const int nblk = blockIdx.y * 2 + warp_n;   // global 32-col n-block

    __shared__ float s_alpha[NT], s_bias[NT];
    if (tid < NT) { s_alpha[tid] = g_alpha[n0 + tid]; s_bias[tid] = bias_g[n0 + tid]; }

    // ---- per-thread cp.async source/dest precompute (A only) ----
    const __half* a_g[4];
    uint32_t sa_off[4];
    #pragma unroll
    for (int q = 0; q < 4; q++) {
        int slot = tid + NTHR * q;
        int row = slot >> 2, seg = slot & 3;
        int p = p0 + row; if (p >= MTOT) p = MTOT - 1;   // clamp (ragged tail)
        int n = p / PIX; int rem = p - n * PIX;
        int h = rem / WW; int w = rem - h * WW;
        a_g[q] = g_xpad + ((size_t)((n * PH + h) * PW + w)) * CIN + seg * 8;
        sa_off[q] = (uint32_t)(row * ROWB + seg * 16);
    }

    // ---- ldmatrix address precompute (A) ----
    uint32_t a_lm[4];
    {
        int rr = lane & 15;
        int ch = (lane >> 4) * 8;
        #pragma unroll
        for (int i = 0; i < 4; i++)
            a_lm[i] = (uint32_t)((warp_m * 64 + i * 16 + rr) * ROWB + ch * 2);
    }

    // packed-B pointer for this lane: [chunk][nblk][kk][lane]
    const uint32_t* bq = g_bq + (size_t)nblk * 64 + lane;   // + chunk*512 + kk*32

    float acc[4][4][4];
    #pragma unroll
    for (int i = 0; i < 4; i++)
        #pragma unroll
        for (int j = 0; j < 4; j++)
            #pragma unroll
            for (int r = 0; r < 4; r++) acc[i][j][r] = 0.f;

    auto fill = [&](int st, int ch) {
        int rs = ch >> 3, cc = ch & 7;
        int r = rs / 3, s = rs - r * 3;
        size_t aoff = (size_t)((r * PW + s) * CIN + cc * KC);
        uint32_t ab = sbase + st * STG;
        #pragma unroll
        for (int q = 0; q < 4; q++) cp16(ab + sa_off[q], a_g[q] + aoff);
        CP_COMMIT();
    };

    // ---- pipelined mainloop: 3 A-stages in flight, B packed 1 chunk ahead ----
    fill(0, 0); fill(1, 1); fill(2, 2);
    uint32_t pq0 = __ldg(bq + 0 * 512 + 0);
    uint32_t pq1 = __ldg(bq + 0 * 512 + 32);

    int st = 0;
    #pragma unroll 1
    for (int ch = 0; ch < NCH; ch++) {
        CP_WAIT(2);
        __syncthreads();
        if (ch + 3 < NCH) fill((st + 3) & (NS - 1), ch + 3);
        else              CP_COMMIT();

        // prefetch next chunk's packed B
        uint32_t nq0 = pq0, nq1 = pq1;
        if (ch + 1 < NCH) {
            nq0 = __ldg(bq + (ch + 1) * 512 + 0);
            nq1 = __ldg(bq + (ch + 1) * 512 + 32);
        }

        uint32_t ab = sbase + st * STG;
        #pragma unroll
        for (int kk = 0; kk < 2; kk++) {
            uint32_t p = kk ? pq1 : pq0;
            // decode B fragments: reg (j2,rr) from bits 8*j2 + 4*rr
            uint32_t breg[8];
            #pragma unroll
            for (int j2 = 0; j2 < 4; j2++) {
                breg[j2 * 2]     = dec2(p >> (8 * j2));
                breg[j2 * 2 + 1] = dec2(p >> (8 * j2 + 4));
            }
            uint32_t a[4][4];
            #pragma unroll
            for (int i = 0; i < 4; i++) LDSM4(a[i], ab + a_lm[i] + kk * 32);
            #pragma unroll
            for (int i = 0; i < 4; i++)
                #pragma unroll
                for (int j2 = 0; j2 < 4; j2++)
                    MMA16816(acc[i][j2], a[i], breg[j2 * 2], breg[j2 * 2 + 1]);
        }
        pq0 = nq0; pq1 = nq1;
        st = (st + 1) & (NS - 1);
    }
    __syncthreads();

    // ---- epilogue: stage through smem, out = alpha*acc + bias ----
    float* stile = (float*)smem;   // [192][65] = 49.9KB <= 61.4KB dyn smem
    #pragma unroll
    for (int i = 0; i < 4; i++)
        #pragma unroll
        for (int j2 = 0; j2 < 4; j2++) {
            int no = warp_n * 32 + j2 * 8 + (lane & 3) * 2;
            int m0 = warp_m * 64 + i * 16 + (lane >> 2);
            stile[m0 * 65 + no]           = acc[i][j2][0];
            stile[m0 * 65 + no + 1]       = acc[i][j2][1];
            stile[(m0 + 8) * 65 + no]     = acc[i][j2][2];
            stile[(m0 + 8) * 65 + no + 1] = acc[i][j2][3];
        }
    __syncthreads();

    int p = p0 + tid;
    if (p < MTOT) {
        int nimg = p / PIX; int hw = p - nimg * PIX;
        float* ob = out + ((size_t)nimg * KOUT + n0) * PIX + hw;
        #pragma unroll
        for (int k = 0; k < NT; k++) {
            float v = stile[tid * 65 + k];
            ob[(size_t)k * PIX] = fmaf(s_alpha[k], v, s_bias[k]);
        }
    }
}

// ---------------------------------------------------------------------------
extern "C" void kernel_launch(void* const* d_in, const int* in_sizes, int n_in,
                              void* d_out, int out_size) {
    const float* x      = (const float*)d_in[0];
    const float* weight = (const float*)d_in[1];
    const float* bias   = (const float*)d_in[2];
    float* out          = (float*)d_out;

    cudaFuncSetAttribute(conv_mma_kernel,
                         cudaFuncAttributeMaxDynamicSharedMemorySize, SMDYN);

    ternarize_kernel<<<KOUT, 256>>>(weight);
    pack_b_kernel<<<dim3(NCH, 8), 64>>>();
    pad_transpose_kernel<<<dim3(PH, 4, NIMG), 256>>>(x);
    const int mtiles = (MTOT + MT - 1) / MT;   // 523
    conv_mma_kernel<<<dim3(mtiles, KOUT / NT), NTHR, SMDYN>>>(bias, out);
}

// round 14
// speedup vs baseline: 1.1416x; 1.1416x over previous
#include <cuda_runtime.h>
#include <cuda_fp16.h>
#include <cstdint>

// ---------------- problem constants ----------------
#define CIN   256
#define KOUT  256
#define HH    56
#define WW    56
#define NPF   2304           // 256*3*3 per output filter
#define PH    58
#define PW    58
#define NIMG  32
#define PIX   (HH*WW)        // 3136
#define MTOT  (NIMG*PIX)     // 100352

// ---------------- GEMM tiling ----------------
#define MT    192            // CTA M tile (ragged tail: last tile covers 128)
#define NT    64             // CTA N tile
#define KC    64             // K chunk (halfs)  -- doubled vs R11
#define NCH   36             // 9 taps * 4 chunks of 64 channels
#define NS    3              // pipeline stages
#define NTHR  192            // 6 warps (3m x 2n); 2 CTAs/SM -> 170 regs/thread

// smem stage: A(192 rows x 144B) + B(64 rows x 144B); 144B stride (36 words)
// -> successive rows hit distinct 4-bank groups: conflict-free LDSM/cp.async
#define ROWB  144
#define ASTG  (MT*ROWB)      // 27648
#define BSTG  (NT*ROWB)      // 9216
#define STG   (ASTG+BSTG)    // 36864
#define SMDYN (NS*STG)       // 110592

// ---------------- device scratch ----------------
__device__ __half g_b[9 * KOUT * CIN];                   // [rs][k][c], +-1
__device__ float  g_alpha[KOUT];
__device__ __half g_xpad[(size_t)NIMG * PH * PW * CIN];  // [n][hp][wp][c]

// ---------------- ptx helpers (family-portable only) ----------------
__device__ __forceinline__ void cp16(uint32_t dst, const void* src) {
    asm volatile("cp.async.cg.shared.global [%0], [%1], 16;"
                 :: "r"(dst), "l"(__cvta_generic_to_global(src)) : "memory");
}
#define CP_COMMIT()  asm volatile("cp.async.commit_group;" ::: "memory")
#define CP_WAIT(N)   asm volatile("cp.async.wait_group %0;" :: "n"(N) : "memory")

#define LDSM4(R, addr)                                                        \
    asm volatile("ldmatrix.sync.aligned.m8n8.x4.shared.b16 {%0,%1,%2,%3}, [%4];" \
                 : "=r"((R)[0]), "=r"((R)[1]), "=r"((R)[2]), "=r"((R)[3])     \
                 : "r"(addr))

#define MMA16816(D, A, B0, B1)                                                \
    asm volatile("mma.sync.aligned.m16n8k16.row.col.f32.f16.f16.f32 "         \
                 "{%0,%1,%2,%3}, {%4,%5,%6,%7}, {%8,%9}, {%0,%1,%2,%3};"      \
                 : "+f"((D)[0]), "+f"((D)[1]), "+f"((D)[2]), "+f"((D)[3])     \
                 : "r"((A)[0]), "r"((A)[1]), "r"((A)[2]), "r"((A)[3]),        \
                   "r"(B0), "r"(B1))

// ---------------------------------------------------------------------------
// K0: ternarize (float4 + warp shuffle reductions). One block per filter.
// ---------------------------------------------------------------------------
__global__ void ternarize_kernel(const float* __restrict__ w) {
    const int o = blockIdx.x;
    const int tid = threadIdx.x;
    const int lane = tid & 31;
    const int wrp = tid >> 5;
    const float4* wo4 = (const float4*)(w + (size_t)o * NPF);
    __shared__ float red[8];
    __shared__ float s_delta;

    float s = 0.f;
    for (int i = tid; i < NPF / 4; i += 256) {
        float4 v = wo4[i];
        s += fabsf(v.x) + fabsf(v.y) + fabsf(v.z) + fabsf(v.w);
    }
    #pragma unroll
    for (int d = 16; d > 0; d >>= 1) s += __shfl_xor_sync(~0u, s, d);
    if (lane == 0) red[wrp] = s;
    __syncthreads();
    if (tid == 0) {
        float t = 0.f;
        #pragma unroll
        for (int i = 0; i < 8; i++) t += red[i];
        s_delta = (0.7f / (float)NPF) * t;
    }
    __syncthreads();
    const float delta = s_delta;

    float cnt = 0.f, asum = 0.f;
    for (int i = tid; i < NPF / 4; i += 256) {
        float4 v = wo4[i];
        float a;
        a = fabsf(v.x); if (a > delta) { cnt += 1.f; asum += a; }
        a = fabsf(v.y); if (a > delta) { cnt += 1.f; asum += a; }
        a = fabsf(v.z); if (a > delta) { cnt += 1.f; asum += a; }
        a = fabsf(v.w); if (a > delta) { cnt += 1.f; asum += a; }
    }
    #pragma unroll
    for (int d = 16; d > 0; d >>= 1) {
        cnt  += __shfl_xor_sync(~0u, cnt, d);
        asum += __shfl_xor_sync(~0u, asum, d);
    }
    if (lane == 0) red[wrp] = cnt;
    __syncthreads();
    float cnt_tot = 0.f;
    if (tid == 0) {
        #pragma unroll
        for (int i = 0; i < 8; i++) cnt_tot += red[i];
        red[0] = cnt_tot;
    }
    __syncthreads();
    cnt_tot = red[0];
    __syncthreads();
    if (lane == 0) red[wrp] = asum;
    __syncthreads();
    if (tid == 0) {
        float t = 0.f;
        #pragma unroll
        for (int i = 0; i < 8; i++) t += red[i];
        g_alpha[o] = t / cnt_tot;
    }

    const float* wo = w + (size_t)o * NPF;
    for (int i = tid; i < NPF; i += 256) {
        float v = wo[i];
        float t = (v > delta) ? 1.f : ((v < -delta) ? -1.f : 0.f);
        int c = i / 9, rs = i % 9;
        g_b[((size_t)rs * KOUT + o) * CIN + c] = __float2half_rn(t);
    }
}

// ---------------------------------------------------------------------------
// K1: pad + NCHW->NHWC transpose + fp16 convert (border rows write zeros).
// ---------------------------------------------------------------------------
__global__ void pad_transpose_kernel(const float* __restrict__ x) {
    __shared__ float s[64][57];
    const int hp = blockIdx.x, c0 = blockIdx.y * 64, n = blockIdx.z;
    __half* dst = g_xpad + ((size_t)(n * PH + hp) * PW) * CIN + c0;

    if (hp == 0 || hp == PH - 1) {
        for (int idx = threadIdx.x; idx < PW * 8; idx += 256) {
            int wp = idx >> 3, u = idx & 7;
            ((uint4*)(dst + (size_t)wp * CIN))[u] = make_uint4(0u, 0u, 0u, 0u);
        }
        return;
    }

    const int h = hp - 1;
    const float* xp = x + ((size_t)(n * CIN + c0) * HH + h) * WW;
    for (int idx = threadIdx.x; idx < 64 * WW; idx += 256) {
        int ci = idx / WW, w = idx - ci * WW;
        s[ci][w] = xp[(size_t)ci * PIX + w];
    }
    __syncthreads();

    for (int idx = threadIdx.x; idx < PW * 64; idx += 256) {
        int wp = idx / 64, ci = idx - wp * 64;
        float v = (wp >= 1 && wp <= WW) ? s[ci][wp - 1] : 0.f;
        dst[(size_t)wp * CIN + ci] = __float2half_rn(v);
    }
}

// ---------------------------------------------------------------------------
// K2: implicit-GEMM conv via mma.sync m16n8k16 (fp32 acc).
// Grid (523, 4): CTA = 192 x 64. 6 warps (3m x 2n), warp 64x32, 2 CTAs/SM.
// KC=64: one CP_WAIT+barrier per 64 MMAs/warp (half the fixed overhead of
// KC=32). Fragments double-buffered across the 4 kk steps.
// ---------------------------------------------------------------------------
__global__ void __launch_bounds__(NTHR, 2)
conv_mma_kernel(const float* __restrict__ bias_g, float* __restrict__ out) {
    extern __shared__ __align__(128) char smem[];
    const uint32_t sbase = (uint32_t)__cvta_generic_to_shared(smem);

    const int tid = threadIdx.x;
    const int lane = tid & 31;
    const int wid = tid >> 5;           // 0..5
    const int warp_m = wid >> 1;        // 0..2
    const int warp_n = wid & 1;         // 0..1

    const int p0 = blockIdx.x * MT;
    const int n0 = blockIdx.y * NT;

    __shared__ float s_alpha[NT], s_bias[NT];
    if (tid < NT) { s_alpha[tid] = g_alpha[n0 + tid]; s_bias[tid] = bias_g[n0 + tid]; }

    // ---- per-thread cp.async source/dest precompute ----
    // A: 192 rows x 8 segs(16B) = 1536 slots / 192 thr = 8 each
    const __half* a_g[8];
    uint32_t sa_off[8];
    #pragma unroll
    for (int q = 0; q < 8; q++) {
        int slot = tid + NTHR * q;
        int row = slot >> 3, seg = slot & 7;
        int p = p0 + row; if (p >= MTOT) p = MTOT - 1;   // clamp (ragged tail)
        int n = p / PIX; int rem = p - n * PIX;
        int h = rem / WW; int w = rem - h * WW;
        a_g[q] = g_xpad + ((size_t)((n * PH + h) * PW + w)) * CIN + seg * 8;
        sa_off[q] = (uint32_t)(row * ROWB + seg * 16);
    }
    // B: 64 rows x 8 segs = 512 slots: q=0,1 all threads, q=2 only tid<128
    const __half* b_g[3];
    uint32_t sb_off[3];
    #pragma unroll
    for (int q = 0; q < 3; q++) {
        int slot = tid + NTHR * q; if (slot >= 512) slot = 0;
        int row = slot >> 3, seg = slot & 7;
        b_g[q] = g_b + (size_t)(n0 + row) * CIN + seg * 8;
        sb_off[q] = (uint32_t)(row * ROWB + seg * 16);
    }
    const bool bq2 = (tid < 128);

    // ---- ldmatrix address precompute ----
    uint32_t a_lm[4];
    {
        int rr = lane & 15;
        int ch = (lane >> 4) * 8;
        #pragma unroll
        for (int i = 0; i < 4; i++)
            a_lm[i] = (uint32_t)((warp_m * 64 + i * 16 + rr) * ROWB + ch * 2);
    }
    uint32_t b_lm[2];
    {
        int nn = (lane & 7) + ((lane & 16) >> 1);
        int kk0 = lane & 8;
        #pragma unroll
        for (int j = 0; j < 2; j++)
            b_lm[j] = (uint32_t)((warp_n * 32 + j * 16 + nn) * ROWB + kk0 * 2);
    }

    float acc[4][4][4];
    #pragma unroll
    for (int i = 0; i < 4; i++)
        #pragma unroll
        for (int j = 0; j < 4; j++)
            #pragma unroll
            for (int r = 0; r < 4; r++) acc[i][j][r] = 0.f;

    auto fill = [&](int st, int ch) {
        int rs = ch >> 2, cc = ch & 3;
        int r = rs / 3, s = rs - r * 3;
        size_t aoff = (size_t)((r * PW + s) * CIN + cc * KC);
        size_t boff = (size_t)rs * (KOUT * CIN) + cc * KC;
        uint32_t ab = sbase + st * STG;
        uint32_t bb = ab + ASTG;
        #pragma unroll
        for (int q = 0; q < 8; q++) cp16(ab + sa_off[q], a_g[q] + aoff);
        cp16(bb + sb_off[0], b_g[0] + boff);
        cp16(bb + sb_off[1], b_g[1] + boff);
        if (bq2) cp16(bb + sb_off[2], b_g[2] + boff);
        CP_COMMIT();
    };

    // ---- pipelined mainloop: NS=3, prefetch distance 2 ----
    fill(0, 0); fill(1, 1);

    int st = 0;
    #pragma unroll 1
    for (int ch = 0; ch < NCH; ch++) {
        CP_WAIT(1);
        __syncthreads();
        if (ch + 2 < NCH) fill((st + 2) % NS, ch + 2);
        else              CP_COMMIT();

        uint32_t ab = sbase + st * STG;
        uint32_t bb = ab + ASTG;

        // 4 kk steps of K=16, fragments double-buffered (2-deep)
        uint32_t a[2][4][4], b[2][2][4];
        #pragma unroll
        for (int i = 0; i < 4; i++) LDSM4(a[0][i], ab + a_lm[i]);
        #pragma unroll
        for (int j = 0; j < 2; j++) LDSM4(b[0][j], bb + b_lm[j]);

        #pragma unroll
        for (int kk = 0; kk < 4; kk++) {
            int cur = kk & 1, nxt = cur ^ 1;
            if (kk < 3) {
                #pragma unroll
                for (int i = 0; i < 4; i++)
                    LDSM4(a[nxt][i], ab + a_lm[i] + (kk + 1) * 32);
                #pragma unroll
                for (int j = 0; j < 2; j++)
                    LDSM4(b[nxt][j], bb + b_lm[j] + (kk + 1) * 32);
            }
            #pragma unroll
            for (int i = 0; i < 4; i++)
                #pragma unroll
                for (int j2 = 0; j2 < 4; j2++)
                    MMA16816(acc[i][j2], a[cur][i],
                             b[cur][j2 >> 1][(j2 & 1) * 2],
                             b[cur][j2 >> 1][(j2 & 1) * 2 + 1]);
        }
        st++; if (st == NS) st = 0;
    }
    __syncthreads();

    // ---- epilogue: stage through smem, out = alpha*acc + bias ----
    float* stile = (float*)smem;   // [192][65] = 49.9KB <= 110.6KB dyn smem
    #pragma unroll
    for (int i = 0; i < 4; i++)
        #pragma unroll
        for (int j2 = 0; j2 < 4; j2++) {
            int no = warp_n * 32 + j2 * 8 + (lane & 3) * 2;
            int m0 = warp_m * 64 + i * 16 + (lane >> 2);
            stile[m0 * 65 + no]           = acc[i][j2][0];
            stile[m0 * 65 + no + 1]       = acc[i][j2][1];
            stile[(m0 + 8) * 65 + no]     = acc[i][j2][2];
            stile[(m0 + 8) * 65 + no + 1] = acc[i][j2][3];
        }
    __syncthreads();

    int p = p0 + tid;
    if (p < MTOT) {
        int nimg = p / PIX; int hw = p - nimg * PIX;
        float* ob = out + ((size_t)nimg * KOUT + n0) * PIX + hw;
        #pragma unroll
        for (int k = 0; k < NT; k++) {
            float v = stile[tid * 65 + k];
            ob[(size_t)k * PIX] = fmaf(s_alpha[k], v, s_bias[k]);
        }
    }
}

// ---------------------------------------------------------------------------
extern "C" void kernel_launch(void* const* d_in, const int* in_sizes, int n_in,
                              void* d_out, int out_size) {
    const float* x      = (const float*)d_in[0];
    const float* weight = (const float*)d_in[1];
    const float* bias   = (const float*)d_in[2];
    float* out          = (float*)d_out;

    cudaFuncSetAttribute(conv_mma_kernel,
                         cudaFuncAttributeMaxDynamicSharedMemorySize, SMDYN);

    ternarize_kernel<<<KOUT, 256>>>(weight);
    pad_transpose_kernel<<<dim3(PH, 4, NIMG), 256>>>(x);
    const int mtiles = (MTOT + MT - 1) / MT;   // 523
    conv_mma_kernel<<<dim3(mtiles, KOUT / NT), NTHR, SMDYN>>>(bias, out);
}

// round 15
// speedup vs baseline: 1.3172x; 1.1538x over previous
#include <cuda_runtime.h>
#include <cuda_fp16.h>
#include <cstdint>

// ---------------- problem constants ----------------
#define CIN   256
#define KOUT  256
#define HH    56
#define WW    56
#define NPF   2304           // 256*3*3 per output filter
#define PH    58
#define PW    58
#define NIMG  32
#define PIX   (HH*WW)        // 3136
#define MTOT  (NIMG*PIX)     // 100352

// ---------------- tiling ----------------
#define MT    224            // = 4*56: every tile row-aligned, 448 tiles exact
#define NT    64             // CTA N tile
#define NTHR  224            // 7 warps, each 32(m) x 64(n); 2 CTAs/SM

// A stage: 6 input rows x 58 wp x 64B payload @80B stride (conflict-free)
#define AROW  80
#define AST   (6*58*AROW)    // 27840
// B sub-stage: 3 taps x 64 n-rows x 64B @80B stride
#define BST   (3*64*AROW)    // 15360
#define SMDYN (2*AST + 2*BST)  // 86400 (epilogue stile 224*65*4=58240 fits)

// ---------------- device scratch ----------------
__device__ __half g_b[9 * KOUT * CIN];                   // [rs][k][c], +-1
__device__ float  g_alpha[KOUT];
__device__ __half g_xpad[(size_t)NIMG * PH * PW * CIN];  // [n][hp][wp][c]

// ---------------- ptx helpers (family-portable only) ----------------
__device__ __forceinline__ void cp16(uint32_t dst, const void* src) {
    asm volatile("cp.async.cg.shared.global [%0], [%1], 16;"
                 :: "r"(dst), "l"(__cvta_generic_to_global(src)) : "memory");
}
#define CP_COMMIT()  asm volatile("cp.async.commit_group;" ::: "memory")
#define CP_WAIT(N)   asm volatile("cp.async.wait_group %0;" :: "n"(N) : "memory")

#define LDSM4(R, addr)                                                        \
    asm volatile("ldmatrix.sync.aligned.m8n8.x4.shared.b16 {%0,%1,%2,%3}, [%4];" \
                 : "=r"((R)[0]), "=r"((R)[1]), "=r"((R)[2]), "=r"((R)[3])     \
                 : "r"(addr))

#define MMA16816(D, A, B0, B1)                                                \
    asm volatile("mma.sync.aligned.m16n8k16.row.col.f32.f16.f16.f32 "         \
                 "{%0,%1,%2,%3}, {%4,%5,%6,%7}, {%8,%9}, {%0,%1,%2,%3};"      \
                 : "+f"((D)[0]), "+f"((D)[1]), "+f"((D)[2]), "+f"((D)[3])     \
                 : "r"((A)[0]), "r"((A)[1]), "r"((A)[2]), "r"((A)[3]),        \
                   "r"(B0), "r"(B1))

// ---------------------------------------------------------------------------
// K0: ternarize (float4 + warp shuffle reductions). One block per filter.
// ---------------------------------------------------------------------------
__global__ void ternarize_kernel(const float* __restrict__ w) {
    const int o = blockIdx.x;
    const int tid = threadIdx.x;
    const int lane = tid & 31;
    const int wrp = tid >> 5;
    const float4* wo4 = (const float4*)(w + (size_t)o * NPF);
    __shared__ float red[8];
    __shared__ float s_delta;

    float s = 0.f;
    for (int i = tid; i < NPF / 4; i += 256) {
        float4 v = wo4[i];
        s += fabsf(v.x) + fabsf(v.y) + fabsf(v.z) + fabsf(v.w);
    }
    #pragma unroll
    for (int d = 16; d > 0; d >>= 1) s += __shfl_xor_sync(~0u, s, d);
    if (lane == 0) red[wrp] = s;
    __syncthreads();
    if (tid == 0) {
        float t = 0.f;
        #pragma unroll
        for (int i = 0; i < 8; i++) t += red[i];
        s_delta = (0.7f / (float)NPF) * t;
    }
    __syncthreads();
    const float delta = s_delta;

    float cnt = 0.f, asum = 0.f;
    for (int i = tid; i < NPF / 4; i += 256) {
        float4 v = wo4[i];
        float a;
        a = fabsf(v.x); if (a > delta) { cnt += 1.f; asum += a; }
        a = fabsf(v.y); if (a > delta) { cnt += 1.f; asum += a; }
        a = fabsf(v.z); if (a > delta) { cnt += 1.f; asum += a; }
        a = fabsf(v.w); if (a > delta) { cnt += 1.f; asum += a; }
    }
    #pragma unroll
    for (int d = 16; d > 0; d >>= 1) {
        cnt  += __shfl_xor_sync(~0u, cnt, d);
        asum += __shfl_xor_sync(~0u, asum, d);
    }
    if (lane == 0) red[wrp] = cnt;
    __syncthreads();
    float cnt_tot = 0.f;
    if (tid == 0) {
        #pragma unroll
        for (int i = 0; i < 8; i++) cnt_tot += red[i];
        red[0] = cnt_tot;
    }
    __syncthreads();
    cnt_tot = red[0];
    __syncthreads();
    if (lane == 0) red[wrp] = asum;
    __syncthreads();
    if (tid == 0) {
        float t = 0.f;
        #pragma unroll
        for (int i = 0; i < 8; i++) t += red[i];
        g_alpha[o] = t / cnt_tot;
    }

    const float* wo = w + (size_t)o * NPF;
    for (int i = tid; i < NPF; i += 256) {
        float v = wo[i];
        float t = (v > delta) ? 1.f : ((v < -delta) ? -1.f : 0.f);
        int c = i / 9, rs = i % 9;
        g_b[((size_t)rs * KOUT + o) * CIN + c] = __float2half_rn(t);
    }
}

// ---------------------------------------------------------------------------
// K1: pad + NCHW->NHWC transpose + fp16 convert (border rows write zeros).
// ---------------------------------------------------------------------------
__global__ void pad_transpose_kernel(const float* __restrict__ x) {
    __shared__ float s[64][57];
    const int hp = blockIdx.x, c0 = blockIdx.y * 64, n = blockIdx.z;
    __half* dst = g_xpad + ((size_t)(n * PH + hp) * PW) * CIN + c0;

    if (hp == 0 || hp == PH - 1) {
        for (int idx = threadIdx.x; idx < PW * 8; idx += 256) {
            int wp = idx >> 3, u = idx & 7;
            ((uint4*)(dst + (size_t)wp * CIN))[u] = make_uint4(0u, 0u, 0u, 0u);
        }
        return;
    }

    const int h = hp - 1;
    const float* xp = x + ((size_t)(n * CIN + c0) * HH + h) * WW;
    for (int idx = threadIdx.x; idx < 64 * WW; idx += 256) {
        int ci = idx / WW, w = idx - ci * WW;
        s[ci][w] = xp[(size_t)ci * PIX + w];
    }
    __syncthreads();

    for (int idx = threadIdx.x; idx < PW * 64; idx += 256) {
        int wp = idx / 64, ci = idx - wp * 64;
        float v = (wp >= 1 && wp <= WW) ? s[ci][wp - 1] : 0.f;
        dst[(size_t)wp * CIN + ci] = __float2half_rn(v);
    }
}

// ---------------------------------------------------------------------------
// K2: implicit-GEMM conv, 2D-halo A reuse across all 9 taps.
// Grid (448, 4): CTA = 224 pixels (4 full w-rows, image-aligned) x 64 chans.
// 7 warps, each 32(m) x 64(n). Loop: 8 cc x 3 tap-groups; A (6x58 halo)
// loaded ONCE per cc, taps = uniform smem offsets r*4640 + s*80.
// ---------------------------------------------------------------------------
__global__ void __launch_bounds__(NTHR, 2)
conv_mma_kernel(const float* __restrict__ bias_g, float* __restrict__ out) {
    extern __shared__ __align__(128) char smem[];
    const uint32_t sb = (uint32_t)__cvta_generic_to_shared(smem);

    const int tid = threadIdx.x;
    const int lane = tid & 31;
    const int wid = tid >> 5;              // 0..6

    const int p0 = blockIdx.x * MT;        // p0 % 56 == 0, same image
    const int n0 = blockIdx.y * NT;
    const int nimg = p0 / PIX;
    const int h0 = (p0 - nimg * PIX) / WW; // in {0,4,...,52}

    __shared__ float s_alpha[NT], s_bias[NT];
    if (tid < NT)              s_alpha[tid] = g_alpha[n0 + tid];
    else if (tid < 2 * NT)     s_bias[tid - NT] = bias_g[n0 + tid - NT];

    // ---- A fill precompute: 6 slots x 58 wp x 4 segs = 1392 cp16 ----
    const __half* af_src[7];
    uint32_t af_dst[7];
    #pragma unroll
    for (int q = 0; q < 7; q++) {
        int idx = tid + NTHR * q; if (idx >= 1392) idx = 0;
        int slot = idx / 232, rem = idx % 232;
        int wp = rem >> 2, seg = rem & 3;
        af_src[q] = g_xpad + ((size_t)((nimg * PH + (h0 + slot)) * PW + wp)) * CIN
                  + seg * 8;
        af_dst[q] = (uint32_t)(slot * 4640 + wp * AROW + seg * 16);
    }
    // ---- B fill precompute: 3 taps x 64 rows x 4 segs = 768 cp16 ----
    const __half* bf_src[4];
    uint32_t bf_dst[4];
    #pragma unroll
    for (int q = 0; q < 4; q++) {
        int idx = tid + NTHR * q; if (idx >= 768) idx = 0;
        int tap = idx >> 8, rem = idx & 255;
        int row = rem >> 2, seg = rem & 3;
        bf_src[q] = g_b + (size_t)tap * (KOUT * CIN) + (size_t)(n0 + row) * CIN
                  + seg * 8;
        bf_dst[q] = (uint32_t)(tap * 5120 + row * AROW + seg * 16);
    }

    // ---- ldmatrix address precompute ----
    uint32_t a_lm[2];
    #pragma unroll
    for (int i = 0; i < 2; i++) {
        int m = wid * 32 + i * 16 + (lane & 15);
        int j = m / 56, w = m - j * 56;
        a_lm[i] = (uint32_t)(j * 4640 + w * AROW + (lane >> 4) * 16);
    }
    uint32_t b_lm[4];
    {
        int nn = (lane & 7) + ((lane & 16) >> 1);
        int kk0 = lane & 8;
        #pragma unroll
        for (int j = 0; j < 4; j++)
            b_lm[j] = (uint32_t)((j * 16 + nn) * AROW + kk0 * 2);
    }

    float acc[2][8][4];
    #pragma unroll
    for (int i = 0; i < 2; i++)
        #pragma unroll
        for (int j = 0; j < 8; j++)
            #pragma unroll
            for (int r = 0; r < 4; r++) acc[i][j][r] = 0.f;

    auto fillA = [&](int buf, int cc) {
        uint32_t base = sb + buf * AST;
        #pragma unroll
        for (int q = 0; q < 7; q++)
            if (q < 6 || tid < 1392 - 6 * NTHR)
                cp16(base + af_dst[q], af_src[q] + cc * 32);
    };
    auto fillB = [&](int slot, int g, int cc) {
        uint32_t base = sb + 2 * AST + slot * BST;
        size_t off = (size_t)(3 * g) * (KOUT * CIN) + cc * 32;
        #pragma unroll
        for (int q = 0; q < 4; q++)
            if (q < 3 || tid < 768 - 3 * NTHR)
                cp16(base + bf_dst[q], bf_src[q] + off);
    };

    // ---- prologue ----
    fillA(0, 0); fillB(0, 0, 0); CP_COMMIT();

    int G = 0;
    #pragma unroll 1
    for (int cc = 0; cc < 8; cc++) {
        #pragma unroll 1
        for (int g = 0; g < 3; g++) {
            CP_WAIT(0);
            __syncthreads();
            if (g < 2) {
                fillB((G + 1) & 1, g + 1, cc); CP_COMMIT();
            } else if (cc < 7) {
                fillA((cc + 1) & 1, cc + 1);
                fillB((G + 1) & 1, 0, cc + 1); CP_COMMIT();
            }

            uint32_t ab = sb + (cc & 1) * AST;
            uint32_t bb = sb + 2 * AST + (G & 1) * BST;
            #pragma unroll
            for (int t = 0; t < 3; t++) {
                // tap (r=g, s=t): uniform offsets
                uint32_t aoff = (uint32_t)(g * 4640 + t * AROW);
                uint32_t boff = (uint32_t)(t * 5120);
                uint32_t a[2][2][4], b[2][4][4];
                #pragma unroll
                for (int kk = 0; kk < 2; kk++) {
                    #pragma unroll
                    for (int i = 0; i < 2; i++)
                        LDSM4(a[kk][i], ab + a_lm[i] + aoff + kk * 32);
                    #pragma unroll
                    for (int j = 0; j < 4; j++)
                        LDSM4(b[kk][j], bb + boff + b_lm[j] + kk * 32);
                    #pragma unroll
                    for (int i = 0; i < 2; i++)
                        #pragma unroll
                        for (int j = 0; j < 8; j++)
                            MMA16816(acc[i][j], a[kk][i],
                                     b[kk][j >> 1][(j & 1) * 2],
                                     b[kk][j >> 1][(j & 1) * 2 + 1]);
                }
            }
            G++;
        }
    }
    __syncthreads();

    // ---- epilogue: stage through smem, out = alpha*acc + bias ----
    float* stile = (float*)smem;   // [224][65] = 58.2KB <= 86.4KB dyn
    #pragma unroll
    for (int i = 0; i < 2; i++)
        #pragma unroll
        for (int j = 0; j < 8; j++) {
            int no = j * 8 + (lane & 3) * 2;
            int m0 = wid * 32 + i * 16 + (lane >> 2);
            stile[m0 * 65 + no]           = acc[i][j][0];
            stile[m0 * 65 + no + 1]       = acc[i][j][1];
            stile[(m0 + 8) * 65 + no]     = acc[i][j][2];
            stile[(m0 + 8) * 65 + no + 1] = acc[i][j][3];
        }
    __syncthreads();

    const int p = p0 + tid;                 // always < MTOT (exact tiling)
    const int hw = p - nimg * PIX;
    float* ob = out + ((size_t)nimg * KOUT + n0) * PIX + hw;
    #pragma unroll
    for (int k = 0; k < NT; k++) {
        float v = stile[tid * 65 + k];
        ob[(size_t)k * PIX] = fmaf(s_alpha[k], v, s_bias[k]);
    }
}

// ---------------------------------------------------------------------------
extern "C" void kernel_launch(void* const* d_in, const int* in_sizes, int n_in,
                              void* d_out, int out_size) {
    const float* x      = (const float*)d_in[0];
    const float* weight = (const float*)d_in[1];
    const float* bias   = (const float*)d_in[2];
    float* out          = (float*)d_out;

    cudaFuncSetAttribute(conv_mma_kernel,
                         cudaFuncAttributeMaxDynamicSharedMemorySize, SMDYN);

    ternarize_kernel<<<KOUT, 256>>>(weight);
    pad_transpose_kernel<<<dim3(PH, 4, NIMG), 256>>>(x);
    conv_mma_kernel<<<dim3(MTOT / MT, KOUT / NT), NTHR, SMDYN>>>(bias, out);
}